// round 15
// baseline (speedup 1.0000x reference)
#include <cuda_runtime.h>
#include <stdint.h>
#include <math.h>

// Problem constants (fixed by the dataset problem)
#define KST   4096   // number of states
#define NSEQ  8192   // number of sequences
#define SLEN  1024   // sequence length
#define WPB   4      // independent warps per block, ONE SEQUENCE PER WARP:
                     // warp-synchronous sampler (no barriers/shared/atomics)
                     // packaged 4-to-a-CTA to clear the 32-CTA/SM occupancy
                     // cap that throttled the 1-warp-per-CTA version.
#define TPB   (WPB * 32)

// Scratch (allocation-free rule: __device__ globals)
__device__ float g_log_init[KST];
__device__ float g_log_trans[(size_t)KST * KST];   // 64 MB, L2-resident
__device__ uint2 g_step_keys[SLEN];
__device__ float g_partial[4096];                  // per-prep-block max log

// ---------------------------------------------------------------------------
// Threefry-2x32 (20 rounds) — host/prep version
// ---------------------------------------------------------------------------
__host__ __device__ __forceinline__ uint32_t rotl32(uint32_t x, int r) {
#ifdef __CUDA_ARCH__
    return __funnelshift_l(x, x, r);
#else
    return (x << r) | (x >> (32 - r));
#endif
}

__host__ __device__ __forceinline__ void threefry2x32(
    uint32_t k0, uint32_t k1, uint32_t x0, uint32_t x1,
    uint32_t* o0, uint32_t* o1)
{
    const uint32_t k2 = k0 ^ k1 ^ 0x1BD11BDAu;
    x0 += k0; x1 += k1;
#define TF_R(r) { x0 += x1; x1 = rotl32(x1, (r)); x1 ^= x0; }
    TF_R(13) TF_R(15) TF_R(26) TF_R(6)
    x0 += k1; x1 += k2 + 1u;
    TF_R(17) TF_R(29) TF_R(16) TF_R(24)
    x0 += k2; x1 += k0 + 2u;
    TF_R(13) TF_R(15) TF_R(26) TF_R(6)
    x0 += k0; x1 += k1 + 3u;
    TF_R(17) TF_R(29) TF_R(16) TF_R(24)
    x0 += k1; x1 += k2 + 4u;
    TF_R(13) TF_R(15) TF_R(26) TF_R(6)
    x0 += k2; x1 += k0 + 5u;
#undef TF_R
    *o0 = x0; *o1 = x1;
}

// ---------------------------------------------------------------------------
// Prep: logs, step keys, per-block max into g_partial (plain deterministic
// stores — no reset kernel, no atomics needed).
// ---------------------------------------------------------------------------
__global__ void prep_kernel(const float* __restrict__ init_p,
                            const float* __restrict__ trans_p,
                            uint32_t key0x, uint32_t key0y,
                            uint32_t kloopx, uint32_t kloopy)
{
    __shared__ float sred[256];
    const long long idx    = (long long)blockIdx.x * blockDim.x + threadIdx.x;
    const long long stride = (long long)gridDim.x * blockDim.x;
    const long long total  = (long long)KST * KST;

    float lmax = -INFINITY;
    for (long long i = idx; i < total; i += stride) {
        const float l = logf(trans_p[i]);
        g_log_trans[i] = l;
        lmax = fmaxf(lmax, l);
    }
    if (idx < KST) {
        const float l = logf(init_p[idx]);
        g_log_init[idx] = l;
        lmax = fmaxf(lmax, l);
    }
    if (idx < SLEN) {
        if (idx == 0) {
            g_step_keys[0] = make_uint2(key0x, key0y);
        } else {
            uint32_t o0, o1;
            threefry2x32(kloopx, kloopy, 0u, (uint32_t)idx, &o0, &o1);
            g_step_keys[idx] = make_uint2(o0, o1);
        }
    }
    sred[threadIdx.x] = lmax;
    __syncthreads();
    for (int o = 128; o > 0; o >>= 1) {
        if (threadIdx.x < o)
            sred[threadIdx.x] = fmaxf(sred[threadIdx.x], sred[threadIdx.x + o]);
        __syncthreads();
    }
    if (threadIdx.x == 0)
        g_partial[blockIdx.x] = sred[0];
}

// ---------------------------------------------------------------------------
// Conservative bits-threshold from a mapped achieved best value.
// u_thr = exp(-exp(-(vb - R))), heavily under-padded so every skipped
// element is PROVABLY strictly below vb -> argmax unchanged bit-for-bit.
// ---------------------------------------------------------------------------
__device__ __forceinline__ uint32_t thr_from_mapped(unsigned m, float R)
{
    const unsigned ub = (m & 0x80000000u) ? (m & 0x7FFFFFFFu) : ~m;  // unmap
    const float vb = __uint_as_float(ub);
    const float t  = vb - R;
    const float w  = expf(-t);
    const float up = expf(-w) * 0.99998f;                  // >=10x composed err
    uint32_t nt = 0u;
    if (up >= 1.0f) {
        nt = 0xFFFFFFFFu;
    } else if (up > 0.0f) {
        const unsigned mant = __float_as_uint(1.0f + up) & 0x7FFFFFu;
        nt = (mant > 8u) ? ((mant - 8u) << 9) : 0u;        // extra ulp pad
    }
    return nt;   // NaN / nonpositive -> 0 (compute everything)
}

// ---------------------------------------------------------------------------
// Main sampler — ONE SEQUENCE PER WARP, 4 independent warps per CTA.
//  - Loop body identical to the 1-warp-per-CTA version (best per-warp
//    instruction count): no __syncthreads, no shared memory, no atomics;
//    warp-uniform registers (last_sb, best_idx, bthr) are the state.
//  - 4-warp CTAs lift the 32-CTA/SM cap that limited occupancy to 39.7%.
//  - All-SHF threefry; adds on the FMA pipe (IMAD via runtime `one`).
//  - REDUX batch gate; within-batch ballot lowest-lane = lowest k; across
//    batches strict wm > last_sb keeps earlier (smaller-k) winner
//    == XLA first-max. Output bit-identical to R8/R11/R13/R14.
// Output written as float32 (harness output dtype).
// ---------------------------------------------------------------------------
__global__ void __launch_bounds__(TPB)
sample_kernel(float* __restrict__ out, uint32_t one)
{
    const int lane = threadIdx.x & 31;
    const int n    = blockIdx.x * WPB + (threadIdx.x >> 5);   // sequence id

    // R = global max log, reduced from prep's per-block partials (one-time)
    float R;
    {
        float pm = -INFINITY;
#pragma unroll 8
        for (int i = 0; i < 4096 / 32; ++i)
            pm = fmaxf(pm, g_partial[lane + i * 32]);
        for (int o = 16; o > 0; o >>= 1)
            pm = fmaxf(pm, __shfl_xor_sync(0xffffffffu, pm, o));
        R = pm;   // uniform across the warp
    }

    const uint32_t ebase  = (uint32_t)n * (uint32_t)KST;
    const float    TINY32 = 1.17549435e-38f;            // finfo(f32).tiny

    int prev = 0;  // unused at s=0 (uses log_init)

    for (int s = 0; s < SLEN; ++s) {
        const uint2 key = g_step_keys[s];
        const float* __restrict__ row =
            (s == 0) ? g_log_init : (g_log_trans + (size_t)prev * KST);

        // hoisted key-injection constants
        const uint32_t k0 = key.x, k1 = key.y, kx = k0 ^ k1 ^ 0x1BD11BDAu;
        const uint32_t i1b = kx + 1u, i2b = k0 + 2u, i3b = k1 + 3u,
                       i4b = kx + 4u, i5b = k0 + 5u;
        const uint32_t x1base = k1 + ebase + (uint32_t)lane;

        unsigned last_sb  = 0u;   // warp-uniform mapped best; 0 < any real
        int      best_idx = 0;    // warp-uniform argmax
        uint32_t bthr     = 0u;   // candidate iff bits >= bthr

#pragma unroll 4
        for (int j = 0; j < KST / 32; ++j) {            // 128 batches of 32
            // threefry(key, (hi=0, lo=ebase + lane + j*32)); x0 starts at k0
            uint32_t x0 = k0;
            uint32_t x1 = one * (uint32_t)(j * 32) + x1base;
#define TFR(r) { x0 = one * x0 + x1; x1 = __funnelshift_l(x1, x1, (r)) ^ x0; }
            TFR(13) TFR(15) TFR(26) TFR(6)
            x0 = one * x0 + k1; x1 = one * x1 + i1b;
            TFR(17) TFR(29) TFR(16) TFR(24)
            x0 = one * x0 + kx; x1 = one * x1 + i2b;
            TFR(13) TFR(15) TFR(26) TFR(6)
            x0 = one * x0 + k0; x1 = one * x1 + i3b;
            TFR(17) TFR(29) TFR(16) TFR(24)
            x0 = one * x0 + k1; x1 = one * x1 + i4b;
            TFR(13) TFR(15) TFR(26) TFR(6)
            x0 = one * x0 + kx; x1 = one * x1 + i5b;
#undef TFR
            const uint32_t bits = x0 ^ x1;   // partitionable 32-bit path

            // batch gate: uniform branch, passes iff any element passes
            const uint32_t wmax = __reduce_max_sync(0xffffffffu, bits);
            if (wmax >= bthr) {
                const bool pass = (bits >= bthr);
                unsigned mk = 0u;
                if (pass) {
                    // uniform(tiny,1): f = bitcast((bits>>9)|0x3f800000)-1 ;
                    // u = max(tiny, f*(1-tiny)+tiny), (1-tiny)==1.0f exactly
                    const float f = __uint_as_float((bits >> 9) | 0x3f800000u) - 1.0f;
                    const float u = fmaxf(TINY32, f + TINY32);
                    const float g = -logf(-logf(u));    // libdevice logf (XLA-GPU)
                    const float v = g + __ldg(row + (lane + j * 32));
                    const unsigned ub = __float_as_uint(v);
                    mk = (ub & 0x80000000u) ? ~ub : (ub | 0x80000000u);  // order-map
                }
                const unsigned wm = __reduce_max_sync(0xffffffffu, mk);
                // strict >: on cross-batch tie the EARLIER batch (smaller k)
                // wins — identical to the pack-atomicMax ordering.
                if (wm > last_sb) {
                    const unsigned sel = __ballot_sync(0xffffffffu, mk == wm);
                    const int src = __ffs(sel) - 1;     // lowest lane = lowest k
                    best_idx = src + j * 32;
                    last_sb  = wm;
                    bthr     = thr_from_mapped(wm, R);
                }
            }
        }

        prev = best_idx;                     // warp-uniform
        if (lane == 0)
            out[(size_t)n * SLEN + s] = (float)prev;    // harness dtype: f32
    }
}

// ---------------------------------------------------------------------------
extern "C" void kernel_launch(void* const* d_in, const int* in_sizes, int n_in,
                              void* d_out, int out_size)
{
    const float* init_p  = (const float*)d_in[0];
    const float* trans_p = (const float*)d_in[1];
    float*       out     = (float*)d_out;

    // key = jax.random.key(42) -> threefry key (0, 42); partitionable split:
    // child i = full output pair of tf(master, (0, i))
    uint32_t a0, a1, b0, b1;
    threefry2x32(0u, 42u, 0u, 0u, &a0, &a1);   // k0    (first-state categorical)
    threefry2x32(0u, 42u, 0u, 1u, &b0, &b1);   // kloop (fold_in base)

    prep_kernel<<<4096, 256>>>(init_p, trans_p, a0, a1, b0, b1);
    sample_kernel<<<NSEQ / WPB, TPB>>>(out, 1u);
}

// round 16
// speedup vs baseline: 1.9314x; 1.9314x over previous
#include <cuda_runtime.h>
#include <stdint.h>
#include <math.h>

// Problem constants (fixed by the dataset problem)
#define KST   4096   // number of states
#define NSEQ  8192   // number of sequences
#define SLEN  1024   // sequence length
#define TPB   64     // 2 warps/block: continues the winning cooperative
                     // trajectory {256:107.7, 128:99.4} -> straggler max
                     // over 2 warps, block-shared prune state RETAINED.

// Scratch (allocation-free rule: __device__ globals)
__device__ float g_log_init[KST];
__device__ float g_log_trans[(size_t)KST * KST];   // 64 MB, L2-resident
__device__ uint2 g_step_keys[SLEN];
__device__ float g_partial[4096];                  // per-prep-block max log

// ---------------------------------------------------------------------------
// Threefry-2x32 (20 rounds) — host/prep version
// ---------------------------------------------------------------------------
__host__ __device__ __forceinline__ uint32_t rotl32(uint32_t x, int r) {
#ifdef __CUDA_ARCH__
    return __funnelshift_l(x, x, r);
#else
    return (x << r) | (x >> (32 - r));
#endif
}

__host__ __device__ __forceinline__ void threefry2x32(
    uint32_t k0, uint32_t k1, uint32_t x0, uint32_t x1,
    uint32_t* o0, uint32_t* o1)
{
    const uint32_t k2 = k0 ^ k1 ^ 0x1BD11BDAu;
    x0 += k0; x1 += k1;
#define TF_R(r) { x0 += x1; x1 = rotl32(x1, (r)); x1 ^= x0; }
    TF_R(13) TF_R(15) TF_R(26) TF_R(6)
    x0 += k1; x1 += k2 + 1u;
    TF_R(17) TF_R(29) TF_R(16) TF_R(24)
    x0 += k2; x1 += k0 + 2u;
    TF_R(13) TF_R(15) TF_R(26) TF_R(6)
    x0 += k0; x1 += k1 + 3u;
    TF_R(17) TF_R(29) TF_R(16) TF_R(24)
    x0 += k1; x1 += k2 + 4u;
    TF_R(13) TF_R(15) TF_R(26) TF_R(6)
    x0 += k2; x1 += k0 + 5u;
#undef TF_R
    *o0 = x0; *o1 = x1;
}

// ---------------------------------------------------------------------------
// Prep: logs, step keys, per-block max into g_partial (plain deterministic
// stores — no reset kernel, no atomics needed).
// ---------------------------------------------------------------------------
__global__ void prep_kernel(const float* __restrict__ init_p,
                            const float* __restrict__ trans_p,
                            uint32_t key0x, uint32_t key0y,
                            uint32_t kloopx, uint32_t kloopy)
{
    __shared__ float sred[256];
    const long long idx    = (long long)blockIdx.x * blockDim.x + threadIdx.x;
    const long long stride = (long long)gridDim.x * blockDim.x;
    const long long total  = (long long)KST * KST;

    float lmax = -INFINITY;
    for (long long i = idx; i < total; i += stride) {
        const float l = logf(trans_p[i]);
        g_log_trans[i] = l;
        lmax = fmaxf(lmax, l);
    }
    if (idx < KST) {
        const float l = logf(init_p[idx]);
        g_log_init[idx] = l;
        lmax = fmaxf(lmax, l);
    }
    if (idx < SLEN) {
        if (idx == 0) {
            g_step_keys[0] = make_uint2(key0x, key0y);
        } else {
            uint32_t o0, o1;
            threefry2x32(kloopx, kloopy, 0u, (uint32_t)idx, &o0, &o1);
            g_step_keys[idx] = make_uint2(o0, o1);
        }
    }
    sred[threadIdx.x] = lmax;
    __syncthreads();
    for (int o = 128; o > 0; o >>= 1) {
        if (threadIdx.x < o)
            sred[threadIdx.x] = fmaxf(sred[threadIdx.x], sred[threadIdx.x + o]);
        __syncthreads();
    }
    if (threadIdx.x == 0)
        g_partial[blockIdx.x] = sred[0];
}

// ---------------------------------------------------------------------------
// Conservative bits-threshold from a mapped achieved best value.
// u_thr = exp(-exp(-(vb - R))), heavily under-padded so every skipped
// element is PROVABLY strictly below vb -> argmax unchanged bit-for-bit.
// ---------------------------------------------------------------------------
__device__ __forceinline__ uint32_t thr_from_mapped(unsigned m, float R)
{
    const unsigned ub = (m & 0x80000000u) ? (m & 0x7FFFFFFFu) : ~m;  // unmap
    const float vb = __uint_as_float(ub);
    const float t  = vb - R;
    const float w  = expf(-t);
    const float up = expf(-w) * 0.99998f;                  // >=10x composed err
    uint32_t nt = 0u;
    if (up >= 1.0f) {
        nt = 0xFFFFFFFFu;
    } else if (up > 0.0f) {
        const unsigned mant = __float_as_uint(1.0f + up) & 0x7FFFFFu;
        nt = (mant > 8u) ? ((mant - 8u) << 9) : 0u;        // extra ulp pad
    }
    return nt;   // NaN / nonpositive -> 0 (compute everything)
}

// ---------------------------------------------------------------------------
// Main sampler — R13 core (best known) at 64 threads/block.
//  - 2 warps x 64 batches/step: barrier straggler max over 2 warps;
//    block-shared prune state RETAINED (the warp-autonomous variants that
//    dropped it ran 120-187 ms vs 99.4).
//  - All-SHF threefry; adds on the FMA pipe (IMAD via runtime `one`).
//  - Per-batch threshold refresh from the live block-shared best.
//  - REDUX batch gate; BLOCK-shared pack argmax:
//      pack = (mapped_value << 32) | (0x7FFFFFFF - index)
//    atomicMax (value-major; ties -> smaller index == XLA first-max).
//  - ONE __syncthreads per step (3-buffer rotation for race-free reset).
// Output written as float32 (harness output dtype).
// ---------------------------------------------------------------------------
__global__ void __launch_bounds__(TPB)
sample_kernel(float* __restrict__ out, uint32_t one)
{
    const int n    = blockIdx.x;
    const int tid  = threadIdx.x;

    __shared__ unsigned long long s_pack[3];
    __shared__ float s_red[TPB];

    // R = global max log, reduced from prep's per-block partials
    {
        float pm = -INFINITY;
#pragma unroll
        for (int i = 0; i < 4096 / TPB; ++i)
            pm = fmaxf(pm, g_partial[tid + i * TPB]);
        s_red[tid] = pm;
        __syncthreads();
        for (int o = TPB / 2; o > 0; o >>= 1) {
            if (tid < o) s_red[tid] = fmaxf(s_red[tid], s_red[tid + o]);
            __syncthreads();
        }
    }
    const float R = s_red[0];
    if (tid == 0) { s_pack[0] = 0ull; s_pack[1] = 0ull; s_pack[2] = 0ull; }
    __syncthreads();

    const uint32_t ebase  = (uint32_t)n * (uint32_t)KST;
    const float    TINY32 = 1.17549435e-38f;            // finfo(f32).tiny

    int prev = 0;  // unused at s=0 (uses log_init)

    for (int s = 0; s < SLEN; ++s) {
        const uint2 key = g_step_keys[s];
        const float* __restrict__ row =
            (s == 0) ? g_log_init : (g_log_trans + (size_t)prev * KST);

        const int bsel = s - (s / 3) * 3;               // s % 3
        unsigned long long* pk = &s_pack[bsel];
        const uint32_t pk_sa = (uint32_t)__cvta_generic_to_shared(pk);

        // hoisted key-injection constants
        const uint32_t k0 = key.x, k1 = key.y, kx = k0 ^ k1 ^ 0x1BD11BDAu;
        const uint32_t i1b = kx + 1u, i2b = k0 + 2u, i3b = k1 + 3u,
                       i4b = kx + 4u, i5b = k0 + 5u;
        const uint32_t x1base = k1 + ebase + (uint32_t)tid;

        unsigned last_sb = 0u;   // cached block-best (mapped); 0 < any real
        uint32_t bthr    = 0u;   // candidate iff bits >= bthr

#pragma unroll 4
        for (int j = 0; j < KST / TPB; ++j) {           // 64 batches
            // threefry(key, (hi=0, lo=ebase + tid + j*TPB)); x0 starts at k0
            uint32_t x0 = k0;
            uint32_t x1 = one * (uint32_t)(j * TPB) + x1base;
#define TFR(r) { x0 = one * x0 + x1; x1 = __funnelshift_l(x1, x1, (r)) ^ x0; }
            TFR(13) TFR(15) TFR(26) TFR(6)
            x0 = one * x0 + k1; x1 = one * x1 + i1b;
            TFR(17) TFR(29) TFR(16) TFR(24)
            x0 = one * x0 + kx; x1 = one * x1 + i2b;
            TFR(13) TFR(15) TFR(26) TFR(6)
            x0 = one * x0 + k0; x1 = one * x1 + i3b;
            TFR(17) TFR(29) TFR(16) TFR(24)
            x0 = one * x0 + k1; x1 = one * x1 + i4b;
            TFR(13) TFR(15) TFR(26) TFR(6)
            x0 = one * x0 + kx; x1 = one * x1 + i5b;
#undef TFR
            const uint32_t bits = x0 ^ x1;   // partitionable 32-bit path

            // refresh threshold from the live block-shared best (value word)
            {
                unsigned sb;
                asm volatile("ld.shared.b32 %0, [%1+4];" : "=r"(sb) : "r"(pk_sa));
                if (sb > last_sb) { last_sb = sb; bthr = thr_from_mapped(sb, R); }
            }

            // batch gate: uniform branch, passes iff any element passes
            const uint32_t wmax = __reduce_max_sync(0xffffffffu, bits);
            if (wmax >= bthr) {
                const bool pass = (bits >= bthr);
                unsigned mk = 0u;
                if (pass) {
                    // uniform(tiny,1): f = bitcast((bits>>9)|0x3f800000)-1 ;
                    // u = max(tiny, f*(1-tiny)+tiny), (1-tiny)==1.0f exactly
                    const float f = __uint_as_float((bits >> 9) | 0x3f800000u) - 1.0f;
                    const float u = fmaxf(TINY32, f + TINY32);
                    const float g = -logf(-logf(u));    // libdevice logf (XLA-GPU)
                    const float v = g + __ldg(row + (tid + j * TPB));
                    const unsigned ub = __float_as_uint(v);
                    mk = (ub & 0x80000000u) ? ~ub : (ub | 0x80000000u);  // order-map
                }
                const unsigned wm = __reduce_max_sync(0xffffffffu, mk);
                if (wm >= last_sb && wm != 0u) {
                    const unsigned sel = __ballot_sync(0xffffffffu, mk == wm);
                    const int src = __ffs(sel) - 1;     // lowest lane = lowest k
                    const int idx = (tid & ~31) + src + j * TPB;
                    const unsigned long long cand =
                        ((unsigned long long)wm << 32) |
                        (unsigned)(0x7FFFFFFF - idx);
                    atomicMax(pk, cand);
                    last_sb = wm;
                    bthr = thr_from_mapped(wm, R);
                }
            }
        }

        __syncthreads();                     // all atomicMax done; pack final
        const unsigned long long fp = *pk;   // ordered-after-barrier plain read
        prev = 0x7FFFFFFF - (int)(unsigned)(fp & 0xFFFFFFFFull);
        if (tid == 0) {
            out[(size_t)n * SLEN + s] = (float)prev;    // harness dtype: f32
            s_pack[(s + 2) % 3] = 0ull;      // distance-2 reuse: race-free
        }
    }
}

// ---------------------------------------------------------------------------
extern "C" void kernel_launch(void* const* d_in, const int* in_sizes, int n_in,
                              void* d_out, int out_size)
{
    const float* init_p  = (const float*)d_in[0];
    const float* trans_p = (const float*)d_in[1];
    float*       out     = (float*)d_out;

    // key = jax.random.key(42) -> threefry key (0, 42); partitionable split:
    // child i = full output pair of tf(master, (0, i))
    uint32_t a0, a1, b0, b1;
    threefry2x32(0u, 42u, 0u, 0u, &a0, &a1);   // k0    (first-state categorical)
    threefry2x32(0u, 42u, 0u, 1u, &b0, &b1);   // kloop (fold_in base)

    prep_kernel<<<4096, 256>>>(init_p, trans_p, a0, a1, b0, b1);
    sample_kernel<<<NSEQ, TPB>>>(out, 1u);
}